// round 14
// baseline (speedup 1.0000x reference)
#include <cuda_runtime.h>
#include <cuda_fp16.h>
#include <cstddef>
#include <cstdint>

#define NP 65536
#define NE 524288
#define RIGN 4096
#define DT_INV 60.0f
#define PXH 136                       // X pitch in halves (272B rows, 16B aligned, conflict-free)
#define CHUNKH 2048                   // halves per K16 weight chunk
#define SMEMSZ (128 * PXH * 2)        // 34816 bytes

// ---------------- device globals (no allocation allowed) ----------------
__device__ float g_cent[6];
__device__ float g_pooled[128];
__device__ float g_Rmat[9];
__device__ float g_tb[3];
// fp16 effect buffers [p][128]
__device__ __align__(16) __half g_eff1[(size_t)NP * 128];
__device__ __align__(16) __half g_eff2[(size_t)NP * 128];
// f32 fused partials: relP = rp_w0*rel_enc + rp_b ; peP = pp_w0*pe + pp_b
__device__ __align__(16) float g_relP[(size_t)NE * 128];
__device__ __align__(16) float g_peP[(size_t)NP * 128];
// f32 aggregation buffer (atomics)
__device__ __align__(16) float g_agg[(size_t)NP * 128];
// fp16 weight blobs, m16n8k16 B-fragment order: [kc][h][lane][32 halves]
__device__ __align__(16) __half g_bPe0[2 * CHUNKH];
__device__ __align__(16) __half g_bPe1[8 * CHUNKH];
__device__ __align__(16) __half g_bRe0[2 * CHUNKH];
__device__ __align__(16) __half g_bRe1[8 * CHUNKH];
__device__ __align__(16) __half g_bRe2[8 * CHUNKH];
__device__ __align__(16) __half g_bRp[24 * CHUNKH];
__device__ __align__(16) __half g_bPp[16 * CHUNKH];
__device__ __align__(16) __half g_bFl0[8 * CHUNKH];
__device__ __align__(16) __half g_bFl1[8 * CHUNKH];

// ---------------- helpers ----------------
__device__ __forceinline__ void mma_f16(float* d, uint32_t a0, uint32_t a1, uint32_t a2,
                                        uint32_t a3, uint32_t b0, uint32_t b1) {
    asm volatile(
        "mma.sync.aligned.m16n8k16.row.col.f32.f16.f16.f32 "
        "{%0,%1,%2,%3}, {%4,%5,%6,%7}, {%8,%9}, {%0,%1,%2,%3};"
        : "+f"(d[0]), "+f"(d[1]), "+f"(d[2]), "+f"(d[3])
        : "r"(a0), "r"(a1), "r"(a2), "r"(a3), "r"(b0), "r"(b1));
}
__device__ __forceinline__ void red2(float* p, float v0, float v1) {
    asm volatile("red.global.add.v2.f32 [%0], {%1, %2};" :: "l"(p), "f"(v0), "f"(v1) : "memory");
}
__device__ __forceinline__ uint32_t f4word(const float4& v, int w) {
    return (w == 0) ? __float_as_uint(v.x) : (w == 1) ? __float_as_uint(v.y)
         : (w == 2) ? __float_as_uint(v.z) : __float_as_uint(v.w);
}
__device__ __forceinline__ uint32_t packh2(float a, float b) {
    __half2 h = __floats2half2_rn(a, b);
    return *(uint32_t*)&h;
}

// core: D[128,128] += X[128,K] * W^T[K,128]; 8 warps, warp tile 32 rows x 64 feats.
// A via ldmatrix.x4, W streams from global blob with one-chunk register prefetch.
__device__ __forceinline__ void mma_layer(uint32_t sXa, const __half* __restrict__ gW,
                                          int nchunks, float acc[2][8][4]) {
    int lane = threadIdx.x & 31, warp = threadIdx.x >> 5;
    int rb = (warp & 3) * 32, h = warp >> 2;
    int rowA = rb + ((lane >> 3) & 1) * 8 + (lane & 7);
    int kofs = (lane >> 4) * 8;
    uint32_t aBase = sXa + (uint32_t)(rowA * PXH + kofs) * 2;
    const float4* wp = (const float4*)(gW + ((h * 32 + lane) * 32));
    float4 cur[4];
#pragma unroll
    for (int q = 0; q < 4; ++q) cur[q] = __ldg(wp + q);
    for (int kc = 0; kc < nchunks; ++kc) {
        int kn = (kc + 1 < nchunks) ? kc + 1 : kc;
        const float4* wn = (const float4*)((const __half*)wp + (size_t)kn * CHUNKH);
        float4 nxt[4];
#pragma unroll
        for (int q = 0; q < 4; ++q) nxt[q] = __ldg(wn + q);
        uint32_t A[2][4];
#pragma unroll
        for (int mt = 0; mt < 2; ++mt) {
            uint32_t a = aBase + (uint32_t)(mt * 16 * PXH * 2 + kc * 32);
            asm volatile("ldmatrix.sync.aligned.m8n8.x4.shared.b16 {%0,%1,%2,%3}, [%4];"
                         : "=r"(A[mt][0]), "=r"(A[mt][1]), "=r"(A[mt][2]), "=r"(A[mt][3])
                         : "r"(a));
        }
#pragma unroll
        for (int j = 0; j < 8; ++j) {
            uint32_t b0 = f4word(cur[j >> 1], (j & 1) * 2);
            uint32_t b1 = f4word(cur[j >> 1], (j & 1) * 2 + 1);
#pragma unroll
            for (int mt = 0; mt < 2; ++mt)
                mma_f16(acc[mt][j], A[mt][0], A[mt][1], A[mt][2], A[mt][3], b0, b1);
        }
#pragma unroll
        for (int q = 0; q < 4; ++q) cur[q] = nxt[q];
    }
}
__device__ __forceinline__ void acc_zero(float acc[2][8][4]) {
#pragma unroll
    for (int mt = 0; mt < 2; ++mt)
#pragma unroll
        for (int j = 0; j < 8; ++j)
#pragma unroll
            for (int q = 0; q < 4; ++q) acc[mt][j][q] = 0.0f;
}
// (+bias) + relu -> fp16 X in place via stmatrix.x4
template <bool BIAS>
__device__ __forceinline__ void epi_x(uint32_t sXa, float acc[2][8][4],
                                      const float* __restrict__ bias) {
    int lane = threadIdx.x & 31, warp = threadIdx.x >> 5;
    int rb = (warp & 3) * 32, h = warp >> 2;
    int tig = lane & 3;
    int rowS = rb + (lane >> 3) * 8 + (lane & 7);
    uint32_t sBase = sXa + (uint32_t)(rowS * PXH + h * 64) * 2;
#pragma unroll
    for (int j = 0; j < 8; ++j) {
        float bx = 0.f, by = 0.f;
        if (BIAS) {
            int c = h * 64 + j * 8 + tig * 2;
            bx = __ldg(bias + c); by = __ldg(bias + c + 1);
        }
        uint32_t w0 = packh2(fmaxf(acc[0][j][0] + bx, 0.f), fmaxf(acc[0][j][1] + by, 0.f));
        uint32_t w1 = packh2(fmaxf(acc[0][j][2] + bx, 0.f), fmaxf(acc[0][j][3] + by, 0.f));
        uint32_t w2 = packh2(fmaxf(acc[1][j][0] + bx, 0.f), fmaxf(acc[1][j][1] + by, 0.f));
        uint32_t w3 = packh2(fmaxf(acc[1][j][2] + bx, 0.f), fmaxf(acc[1][j][3] + by, 0.f));
        asm volatile("stmatrix.sync.aligned.m8n8.x4.shared.b16 [%0], {%1,%2,%3,%4};"
                     :: "r"(sBase + (uint32_t)(j * 16)), "r"(w0), "r"(w1), "r"(w2), "r"(w3)
                     : "memory");
    }
}
// acc + bias -> f32 fragment store to global (row-major [128] cols)
__device__ __forceinline__ void store_fragP(float* __restrict__ gP, float acc[2][8][4],
                                            const float* __restrict__ bias) {
    int lane = threadIdx.x & 31, warp = threadIdx.x >> 5;
    int rb = (warp & 3) * 32, h = warp >> 2;
    int g = lane >> 2, tig = lane & 3;
#pragma unroll
    for (int j = 0; j < 8; ++j) {
        int c = h * 64 + j * 8 + tig * 2;
        float bx = __ldg(bias + c), by = __ldg(bias + c + 1);
#pragma unroll
        for (int mt = 0; mt < 2; ++mt) {
            int r = rb + mt * 16 + g;
            *(float2*)(gP + (size_t)r * 128 + c) =
                make_float2(acc[mt][j][0] + bx, acc[mt][j][1] + by);
            *(float2*)(gP + (size_t)(r + 8) * 128 + c) =
                make_float2(acc[mt][j][2] + bx, acc[mt][j][3] + by);
        }
    }
}
// init acc from f32 fragment in global
__device__ __forceinline__ void load_fragP(const float* __restrict__ gP, float acc[2][8][4]) {
    int lane = threadIdx.x & 31, warp = threadIdx.x >> 5;
    int rb = (warp & 3) * 32, h = warp >> 2;
    int g = lane >> 2, tig = lane & 3;
#pragma unroll
    for (int j = 0; j < 8; ++j) {
        int c = h * 64 + j * 8 + tig * 2;
#pragma unroll
        for (int mt = 0; mt < 2; ++mt) {
            int r = rb + mt * 16 + g;
            float2 a = *(const float2*)(gP + (size_t)r * 128 + c);
            float2 b = *(const float2*)(gP + (size_t)(r + 8) * 128 + c);
            acc[mt][j][0] = a.x; acc[mt][j][1] = a.y;
            acc[mt][j][2] = b.x; acc[mt][j][3] = b.y;
        }
    }
}
// relu -> vectorized f32 atomic scatter into g_agg[recv] (no bias; already in acc)
__device__ __forceinline__ void epi_scatter_nb(const int* __restrict__ recv, int e0,
                                               float acc[2][8][4]) {
    int lane = threadIdx.x & 31, warp = threadIdx.x >> 5;
    int rb = (warp & 3) * 32, h = warp >> 2;
    int g = lane >> 2, tig = lane & 3;
#pragma unroll
    for (int mt = 0; mt < 2; ++mt) {
        int ra = rb + mt * 16 + g;
        int va = __ldg(recv + e0 + ra), vb = __ldg(recv + e0 + ra + 8);
        float* pa = g_agg + (size_t)va * 128;
        float* pb = g_agg + (size_t)vb * 128;
#pragma unroll
        for (int j = 0; j < 8; ++j) {
            int c = h * 64 + j * 8 + tig * 2;
            red2(pa + c, fmaxf(acc[mt][j][0], 0.f), fmaxf(acc[mt][j][1], 0.f));
            red2(pb + c, fmaxf(acc[mt][j][2], 0.f), fmaxf(acc[mt][j][3], 0.f));
        }
    }
}
// staging copies (256 threads)
__device__ __forceinline__ void copy_out(__half* __restrict__ g, const __half* sX) {
    for (int i = threadIdx.x; i < 2048; i += 256) {
        int r = i >> 4, q = i & 15;
        ((float4*)g)[i] = ((const float4*)sX)[r * 17 + q];
    }
}
__device__ __forceinline__ void s_copy(__half* sX, const __half* __restrict__ g) {
    for (int i = threadIdx.x; i < 2048; i += 256) {
        int r = i >> 4, q = i & 15;
        ((float4*)sX)[r * 17 + q] = ((const float4*)g)[i];
    }
}
// f32 agg -> fp16 smem X
__device__ __forceinline__ void s_copy_cvt(__half* sX, const float* __restrict__ g) {
    for (int i = threadIdx.x; i < 4096; i += 256) {
        int r = i >> 5, q = i & 31;
        float4 v = ((const float4*)g)[i];
        uint2 u;
        u.x = packh2(v.x, v.y); u.y = packh2(v.z, v.w);
        ((uint2*)sX)[r * 34 + q] = u;
    }
}
// gather 128 rows src[idx[e0+r]] (fp16 row-major [p][128]) -> X
__device__ __forceinline__ void s_gather(__half* sX, const __half* __restrict__ src,
                                         const int* __restrict__ idx, int e0) {
    int row = threadIdx.x & 127, kq = threadIdx.x >> 7;
    int p = __ldg(idx + e0 + row);
    const float4* s4 = (const float4*)(src + (size_t)p * 128) + kq * 8;
    float4* d4 = (float4*)(sX + row * PXH) + kq * 8;
#pragma unroll
    for (int q = 0; q < 8; ++q) d4[q] = s4[q];
}

// ---------------- setup: fp16 weight blobs in B-fragment order ----------------
__global__ void k_mkblob(const float* __restrict__ pe_w0, const float* __restrict__ pe_w1,
                         const float* __restrict__ re_w0, const float* __restrict__ re_w1,
                         const float* __restrict__ re_w2, const float* __restrict__ rp_w,
                         const float* __restrict__ pp_w, const float* __restrict__ fl_w0,
                         const float* __restrict__ fl_w1) {
    int b = blockIdx.x;
    const float* src; __half* blob;
    int Kval, base;
    if (b < 2)        { src = pe_w0; blob = g_bPe0; Kval = 15;  base = 0; }
    else if (b < 10)  { src = pe_w1; blob = g_bPe1; Kval = 128; base = 2; }
    else if (b < 12)  { src = re_w0; blob = g_bRe0; Kval = 31;  base = 10; }
    else if (b < 20)  { src = re_w1; blob = g_bRe1; Kval = 128; base = 12; }
    else if (b < 28)  { src = re_w2; blob = g_bRe2; Kval = 128; base = 20; }
    else if (b < 52)  { src = rp_w;  blob = g_bRp;  Kval = 384; base = 28; }
    else if (b < 68)  { src = pp_w;  blob = g_bPp;  Kval = 256; base = 52; }
    else if (b < 76)  { src = fl_w0; blob = g_bFl0; Kval = 128; base = 68; }
    else              { src = fl_w1; blob = g_bFl1; Kval = 128; base = 76; }
    int kc = b - base;
    for (int i = threadIdx.x; i < CHUNKH; i += 256) {
        int h = i >> 10, rr = i & 1023, lane = rr >> 5, q = rr & 31;
        int j = q >> 2, u = q & 3;
        int n = h * 64 + j * 8 + (lane >> 2);
        int k = kc * 16 + (lane & 3) * 2 + (u & 1) + ((u >> 1) << 3);
        float v = (k < Kval) ? src[n * Kval + k] : 0.0f;
        blob[kc * CHUNKH + i] = __float2half_rn(v);
    }
}

__global__ void k_centroid(const float* __restrict__ state) {
    __shared__ float red[256];
    float s[6] = {0, 0, 0, 0, 0, 0};
    for (int r = threadIdx.x; r < RIGN; r += 256)
#pragma unroll
        for (int c = 0; c < 6; ++c) s[c] += state[r * 6 + c];
#pragma unroll
    for (int c = 0; c < 6; ++c) {
        red[threadIdx.x] = s[c];
        __syncthreads();
        for (int off = 128; off > 0; off >>= 1) {
            if (threadIdx.x < off) red[threadIdx.x] += red[threadIdx.x + off];
            __syncthreads();
        }
        if (threadIdx.x == 0) g_cent[c] = red[0] * (1.0f / RIGN);
        __syncthreads();
    }
}

// ---------------- particle encoder (+fused pp chunk 0): 15 -> 128 -> 128 -> peP ----------------
__global__ void __launch_bounds__(256, 2) k_pe(const float* __restrict__ state,
                                               const float* __restrict__ attr,
                                               const float* __restrict__ b0,
                                               const float* __restrict__ b1,
                                               const float* __restrict__ pp_b) {
    extern __shared__ __half sm_[];
    __half* sX = sm_;
    uint32_t sXa = (uint32_t)__cvta_generic_to_shared(sX);
    int t = threadIdx.x;
    int p0 = blockIdx.x * 128;
    {
        int row = t & 127, grp = t >> 7;
        int p = p0 + row;
        __half* xr = sX + row * PXH;
        if (grp == 0) {
#pragma unroll
            for (int c = 0; c < 3; ++c) xr[c] = __float2half_rn(attr[p * 3 + c]);
#pragma unroll
            for (int c = 0; c < 6; ++c) xr[9 + c] = __float2half_rn(state[p * 6 + c]);
        } else {
#pragma unroll
            for (int c = 0; c < 6; ++c) {
                float s = state[p * 6 + c];
                xr[3 + c] = (p < RIGN) ? __float2half_rn(s - g_cent[c]) : __half(0.0f);
            }
            for (int c = 15; c < 32; ++c) xr[c] = __half(0.0f);
        }
    }
    __syncthreads();
    float acc[2][8][4];
    acc_zero(acc);
    mma_layer(sXa, g_bPe0, 2, acc);
    __syncthreads();
    epi_x<true>(sXa, acc, b0);
    __syncthreads();
    acc_zero(acc);
    mma_layer(sXa, g_bPe1, 8, acc);
    __syncthreads();
    epi_x<true>(sXa, acc, b1);
    __syncthreads();
    // fused: peP = pp_w0 * particle_encode + pp_b
    acc_zero(acc);
    mma_layer(sXa, g_bPp, 8, acc);
    store_fragP(g_peP + (size_t)p0 * 128, acc, pp_b);
}

// ---------------- relation encoder (+fused rp chunk 0): 31 -> 128^3 -> relP ----------------
__global__ void __launch_bounds__(256, 2) k_rel(const float* __restrict__ state,
                                                const float* __restrict__ attr,
                                                const float* __restrict__ Ra,
                                                const int* __restrict__ recv,
                                                const int* __restrict__ send,
                                                const float* __restrict__ b0,
                                                const float* __restrict__ b1,
                                                const float* __restrict__ b2,
                                                const float* __restrict__ rp_b) {
    extern __shared__ __half sm_[];
    __half* sX = sm_;
    uint32_t sXa = (uint32_t)__cvta_generic_to_shared(sX);
    int t = threadIdx.x;
    int e0 = blockIdx.x * 128;
    {
        int row = t & 127, grp = t >> 7;
        int e = e0 + row;
        __half* xr = sX + row * PXH;
        if (grp == 0) {
            int rv = __ldg(recv + e);
#pragma unroll
            for (int c = 0; c < 3; ++c) xr[c] = __float2half_rn(attr[rv * 3 + c]);
#pragma unroll
            for (int c = 0; c < 6; ++c) {
                float s = state[rv * 6 + c];
                xr[3 + c] = (rv < RIGN) ? __float2half_rn(s - g_cent[c]) : __half(0.0f);
                xr[18 + c] = __float2half_rn(s);
            }
        } else {
            int sd = __ldg(send + e);
#pragma unroll
            for (int c = 0; c < 3; ++c) xr[9 + c] = __float2half_rn(attr[sd * 3 + c]);
#pragma unroll
            for (int c = 0; c < 6; ++c) {
                float s = state[sd * 6 + c];
                xr[12 + c] = (sd < RIGN) ? __float2half_rn(s - g_cent[c]) : __half(0.0f);
                xr[24 + c] = __float2half_rn(s);
            }
            xr[30] = __float2half_rn(Ra[e]);
            xr[31] = __half(0.0f);
        }
    }
    __syncthreads();
    float acc[2][8][4];
    acc_zero(acc);
    mma_layer(sXa, g_bRe0, 2, acc);
    __syncthreads();
    epi_x<true>(sXa, acc, b0);
    __syncthreads();
    acc_zero(acc);
    mma_layer(sXa, g_bRe1, 8, acc);
    __syncthreads();
    epi_x<true>(sXa, acc, b1);
    __syncthreads();
    acc_zero(acc);
    mma_layer(sXa, g_bRe2, 8, acc);
    __syncthreads();
    epi_x<true>(sXa, acc, b2);
    __syncthreads();
    // fused: relP = rp_w0 * relation_encode + rp_b
    acc_zero(acc);
    mma_layer(sXa, g_bRp, 8, acc);
    store_fragP(g_relP + (size_t)e0 * 128, acc, rp_b);
}

// ---------------- propagation step 1: relu(relP) scatter only ----------------
__global__ void __launch_bounds__(256) k_scat1(const int* __restrict__ recv) {
    int t = threadIdx.x;
    int e = blockIdx.x * 128 + (t >> 1);
    int ch = (t & 1) * 64;
    int rv = __ldg(recv + e);
    const float4* s = (const float4*)(g_relP + (size_t)e * 128 + ch);
    float* d = g_agg + (size_t)rv * 128 + ch;
#pragma unroll
    for (int q = 0; q < 16; ++q) {
        float4 v = __ldg(s + q);
        red2(d + q * 4, fmaxf(v.x, 0.f), fmaxf(v.y, 0.f));
        red2(d + q * 4 + 2, fmaxf(v.z, 0.f), fmaxf(v.w, 0.f));
    }
}

// ---------------- propagation step 2 edge pass: relP + rp_w1*eff_r + rp_w2*eff_s ----------------
__global__ void __launch_bounds__(256, 2) k_prop(const int* __restrict__ recv,
                                                 const int* __restrict__ send,
                                                 const __half* __restrict__ eff) {
    extern __shared__ __half sm_[];
    __half* sX = sm_;
    uint32_t sXa = (uint32_t)__cvta_generic_to_shared(sX);
    int e0 = blockIdx.x * 128;
    s_gather(sX, eff, recv, e0);
    float acc[2][8][4];
    load_fragP(g_relP + (size_t)e0 * 128, acc);
    __syncthreads();
    mma_layer(sXa, g_bRp + 8 * CHUNKH, 8, acc);
    __syncthreads();
    s_gather(sX, eff, send, e0);
    __syncthreads();
    mma_layer(sXa, g_bRp + 16 * CHUNKH, 8, acc);
    epi_scatter_nb(recv, e0, acc);
}

// ---------------- particle update: peP + pp_w1*agg -> relu -> eff ----------------
__global__ void __launch_bounds__(256, 2) k_pupdate(__half* __restrict__ effOut) {
    extern __shared__ __half sm_[];
    __half* sX = sm_;
    uint32_t sXa = (uint32_t)__cvta_generic_to_shared(sX);
    int p0 = blockIdx.x * 128;
    s_copy_cvt(sX, g_agg + (size_t)p0 * 128);
    float acc[2][8][4];
    load_fragP(g_peP + (size_t)p0 * 128, acc);
    __syncthreads();
    mma_layer(sXa, g_bPp + 8 * CHUNKH, 8, acc);
    __syncthreads();
    epi_x<false>(sXa, acc, nullptr);
    __syncthreads();
    copy_out(effOut + (size_t)p0 * 128, sX);
}

// ---------------- rigid pooling + small MLP + rigid output ----------------
__global__ void k_pool(const __half* __restrict__ eff) {
    int f = threadIdx.x;  // 128
    int r0 = blockIdx.x * 128;
    float s = 0.0f;
    for (int r = 0; r < 128; ++r) s += __half2float(eff[(size_t)(r0 + r) * 128 + f]);
    atomicAdd(&g_pooled[f], s);
}

__global__ void k_rigid_mlp(const float* __restrict__ w0, const float* __restrict__ b0,
                            const float* __restrict__ w1, const float* __restrict__ b1,
                            const float* __restrict__ w2, const float* __restrict__ b2) {
    __shared__ float pin[128], h0[128], h1[128], tt[7];
    int t = threadIdx.x;  // 128
    pin[t] = g_pooled[t] * (1.0f / RIGN);
    __syncthreads();
    float s = b0[t];
    for (int k = 0; k < 128; ++k) s = fmaf(w0[t * 128 + k], pin[k], s);
    h0[t] = fmaxf(s, 0.0f);
    __syncthreads();
    s = b1[t];
    for (int k = 0; k < 128; ++k) s = fmaf(w1[t * 128 + k], h0[k], s);
    h1[t] = fmaxf(s, 0.0f);
    __syncthreads();
    if (t < 7) {
        s = b2[t];
        for (int k = 0; k < 128; ++k) s = fmaf(w2[t * 128 + k], h1[k], s);
        tt[t] = s;
    }
    __syncthreads();
    if (t == 0) {
        float qw = tt[0], qx = tt[1], qy = tt[2], qz = tt[3];
        float inv = rsqrtf(qw * qw + qx * qx + qy * qy + qz * qz);
        qw *= inv; qx *= inv; qy *= inv; qz *= inv;
        g_Rmat[0] = 1.0f - 2.0f * (qy * qy + qz * qz);
        g_Rmat[1] = 2.0f * (qx * qy + qz * qw);
        g_Rmat[2] = 2.0f * (qx * qz - qy * qw);
        g_Rmat[3] = 2.0f * (qx * qy - qz * qw);
        g_Rmat[4] = 1.0f - 2.0f * (qx * qx + qz * qz);
        g_Rmat[5] = 2.0f * (qy * qz + qx * qw);
        g_Rmat[6] = 2.0f * (qx * qz + qy * qw);
        g_Rmat[7] = 2.0f * (qy * qz - qx * qw);
        g_Rmat[8] = 1.0f - 2.0f * (qx * qx + qy * qy);
        g_tb[0] = tt[4]; g_tb[1] = tt[5]; g_tb[2] = tt[6];
    }
}

__global__ void k_rigid_out(const float* __restrict__ state, float* __restrict__ out) {
    int i = blockIdx.x * 256 + threadIdx.x;
    if (i >= RIGN) return;
    float c0 = g_cent[0], c1 = g_cent[1], c2 = g_cent[2];
    float p0x = state[i * 6], p0y = state[i * 6 + 1], p0z = state[i * 6 + 2];
    float dx = p0x - c0, dy = p0y - c1, dz = p0z - c2;
    float p1x = dx * g_Rmat[0] + dy * g_Rmat[3] + dz * g_Rmat[6] + g_tb[0] + c0;
    float p1y = dx * g_Rmat[1] + dy * g_Rmat[4] + dz * g_Rmat[7] + g_tb[1] + c1;
    float p1z = dx * g_Rmat[2] + dy * g_Rmat[5] + dz * g_Rmat[8] + g_tb[2] + c2;
    out[i * 3] = (p1x - p0x) * DT_INV;
    out[i * 3 + 1] = (p1y - p0y) * DT_INV;
    out[i * 3 + 2] = (p1z - p0z) * DT_INV;
}

// ---------------- fluid predictor: 128 -> 128 -> 128 -> 3 ----------------
__global__ void __launch_bounds__(256, 2) k_fluid(const __half* __restrict__ eff,
                                                  const float* __restrict__ fb0,
                                                  const float* __restrict__ fb1,
                                                  const float* __restrict__ fw2,
                                                  const float* __restrict__ fb2,
                                                  float* __restrict__ out) {
    extern __shared__ __half sm_[];
    __half* sX = sm_;
    uint32_t sXa = (uint32_t)__cvta_generic_to_shared(sX);
    int t = threadIdx.x;
    s_copy(sX, eff + (size_t)(32 + blockIdx.x) * 16384);
    __syncthreads();
    float acc[2][8][4];
    acc_zero(acc);
    mma_layer(sXa, g_bFl0, 8, acc);
    __syncthreads();
    epi_x<true>(sXa, acc, fb0);
    __syncthreads();
    acc_zero(acc);
    mma_layer(sXa, g_bFl1, 8, acc);
    __syncthreads();
    epi_x<true>(sXa, acc, fb1);
    __syncthreads();
    {
        int row = t & 127, grp = t >> 7;
        int p = RIGN + blockIdx.x * 128 + row;
        const __half* xr = sX + row * PXH;
        for (int ch = grp; ch < 3; ch += 2) {
            float o = __ldg(fb2 + ch);
            const float* wr = fw2 + ch * 128;
            for (int k = 0; k < 128; ++k) o = fmaf(__ldg(wr + k), __half2float(xr[k]), o);
            out[(size_t)p * 3 + ch] = o;
        }
    }
}

// ---------------- launch ----------------
extern "C" void kernel_launch(void* const* d_in, const int* in_sizes, int n_in,
                              void* d_out, int out_size) {
    const float* state = (const float*)d_in[0];
    const float* attr = (const float*)d_in[1];
    const float* Ra = (const float*)d_in[2];
    const int* recv = (const int*)d_in[3];
    const int* send = (const int*)d_in[4];
    const float* pe_w0 = (const float*)d_in[5];
    const float* pe_b0 = (const float*)d_in[6];
    const float* pe_w1 = (const float*)d_in[7];
    const float* pe_b1 = (const float*)d_in[8];
    const float* re_w0 = (const float*)d_in[9];
    const float* re_b0 = (const float*)d_in[10];
    const float* re_w1 = (const float*)d_in[11];
    const float* re_b1 = (const float*)d_in[12];
    const float* re_w2 = (const float*)d_in[13];
    const float* re_b2 = (const float*)d_in[14];
    const float* rp_w = (const float*)d_in[15];
    const float* rp_b = (const float*)d_in[16];
    const float* pp_w = (const float*)d_in[17];
    const float* pp_b = (const float*)d_in[18];
    const float* rg_w0 = (const float*)d_in[19];
    const float* rg_b0 = (const float*)d_in[20];
    const float* rg_w1 = (const float*)d_in[21];
    const float* rg_b1 = (const float*)d_in[22];
    const float* rg_w2 = (const float*)d_in[23];
    const float* rg_b2 = (const float*)d_in[24];
    const float* fl_w0 = (const float*)d_in[25];
    const float* fl_b0 = (const float*)d_in[26];
    const float* fl_w1 = (const float*)d_in[27];
    const float* fl_b1 = (const float*)d_in[28];
    const float* fl_w2 = (const float*)d_in[29];
    const float* fl_b2 = (const float*)d_in[30];
    float* out = (float*)d_out;

    cudaFuncSetAttribute(k_pe, cudaFuncAttributeMaxDynamicSharedMemorySize, SMEMSZ);
    cudaFuncSetAttribute(k_rel, cudaFuncAttributeMaxDynamicSharedMemorySize, SMEMSZ);
    cudaFuncSetAttribute(k_prop, cudaFuncAttributeMaxDynamicSharedMemorySize, SMEMSZ);
    cudaFuncSetAttribute(k_pupdate, cudaFuncAttributeMaxDynamicSharedMemorySize, SMEMSZ);
    cudaFuncSetAttribute(k_fluid, cudaFuncAttributeMaxDynamicSharedMemorySize, SMEMSZ);

    float* aggp; float* pooledp; __half* eff1p; __half* eff2p;
    cudaGetSymbolAddress((void**)&aggp, g_agg);
    cudaGetSymbolAddress((void**)&pooledp, g_pooled);
    cudaGetSymbolAddress((void**)&eff1p, g_eff1);
    cudaGetSymbolAddress((void**)&eff2p, g_eff2);

    k_mkblob<<<84, 256>>>(pe_w0, pe_w1, re_w0, re_w1, re_w2, rp_w, pp_w, fl_w0, fl_w1);
    k_centroid<<<1, 256>>>(state);
    k_pe<<<NP / 128, 256, SMEMSZ>>>(state, attr, pe_b0, pe_b1, pp_b);
    k_rel<<<NE / 128, 256, SMEMSZ>>>(state, attr, Ra, recv, send, re_b0, re_b1, re_b2, rp_b);

    // propagation step 1: effect==0 -> scatter relu(relP) only
    cudaMemsetAsync(aggp, 0, (size_t)NP * 128 * sizeof(float));
    k_scat1<<<NE / 128, 256>>>(recv);
    k_pupdate<<<NP / 128, 256, SMEMSZ>>>(eff1p);

    // propagation step 2
    cudaMemsetAsync(aggp, 0, (size_t)NP * 128 * sizeof(float));
    k_prop<<<NE / 128, 256, SMEMSZ>>>(recv, send, eff1p);
    k_pupdate<<<NP / 128, 256, SMEMSZ>>>(eff2p);

    // rigid branch
    cudaMemsetAsync(pooledp, 0, 128 * sizeof(float));
    k_pool<<<RIGN / 128, 128>>>(eff2p);
    k_rigid_mlp<<<1, 128>>>(rg_w0, rg_b0, rg_w1, rg_b1, rg_w2, rg_b2);
    k_rigid_out<<<RIGN / 256, 256>>>(state, out);

    // fluid branch
    k_fluid<<<(NP - RIGN) / 128, 256, SMEMSZ>>>(eff2p, fl_b0, fl_b1, fl_w2, fl_b2, out);
}

// round 15
// speedup vs baseline: 1.1712x; 1.1712x over previous
#include <cuda_runtime.h>
#include <cuda_fp16.h>
#include <cstddef>
#include <cstdint>

#define NP 65536
#define NE 524288
#define RIGN 4096
#define DT_INV 60.0f
#define PXH 136                       // X pitch in halves (272B rows, 16B aligned, conflict-free)
#define CHUNKH 2048                   // halves per K16 weight chunk
#define SMEMSZ (128 * PXH * 2)        // 34816 bytes

// ---------------- device globals (no allocation allowed) ----------------
__device__ float g_cent[6];
__device__ float g_pooled[128];
__device__ float g_Rmat[9];
__device__ float g_tb[3];
// fp16 effect buffers [p][128]
__device__ __align__(16) __half g_eff1[(size_t)NP * 128];
__device__ __align__(16) __half g_eff2[(size_t)NP * 128];
// f32 fused partials in FRAGMENT-BLOB layout (coalesced):
//   blob[block*16384 + warp*2048 + (j*2+mt)*128 + lane*4 .. +3]
__device__ __align__(16) float g_relP[(size_t)NE * 128];
__device__ __align__(16) float g_peP[(size_t)NP * 128];
// f32 aggregation buffer (atomics)
__device__ __align__(16) float g_agg[(size_t)NP * 128];
// fp16 weight blobs, m16n8k16 B-fragment order: [kc][h][lane][32 halves]
__device__ __align__(16) __half g_bPe0[2 * CHUNKH];
__device__ __align__(16) __half g_bPe1[8 * CHUNKH];
__device__ __align__(16) __half g_bRe0[2 * CHUNKH];
__device__ __align__(16) __half g_bRe1[8 * CHUNKH];
__device__ __align__(16) __half g_bRe2[8 * CHUNKH];
__device__ __align__(16) __half g_bRp[24 * CHUNKH];
__device__ __align__(16) __half g_bPp[16 * CHUNKH];
__device__ __align__(16) __half g_bFl0[8 * CHUNKH];
__device__ __align__(16) __half g_bFl1[8 * CHUNKH];

// ---------------- helpers ----------------
__device__ __forceinline__ void mma_f16(float* d, uint32_t a0, uint32_t a1, uint32_t a2,
                                        uint32_t a3, uint32_t b0, uint32_t b1) {
    asm volatile(
        "mma.sync.aligned.m16n8k16.row.col.f32.f16.f16.f32 "
        "{%0,%1,%2,%3}, {%4,%5,%6,%7}, {%8,%9}, {%0,%1,%2,%3};"
        : "+f"(d[0]), "+f"(d[1]), "+f"(d[2]), "+f"(d[3])
        : "r"(a0), "r"(a1), "r"(a2), "r"(a3), "r"(b0), "r"(b1));
}
__device__ __forceinline__ void red2(float* p, float v0, float v1) {
    asm volatile("red.global.add.v2.f32 [%0], {%1, %2};" :: "l"(p), "f"(v0), "f"(v1) : "memory");
}
__device__ __forceinline__ uint32_t f4word(const float4& v, int w) {
    return (w == 0) ? __float_as_uint(v.x) : (w == 1) ? __float_as_uint(v.y)
         : (w == 2) ? __float_as_uint(v.z) : __float_as_uint(v.w);
}
__device__ __forceinline__ uint32_t packh2(float a, float b) {
    __half2 h = __floats2half2_rn(a, b);
    return *(uint32_t*)&h;
}

// core: D[128,128] += X[128,K] * W^T[K,128]; 8 warps, warp tile 32 rows x 64 feats.
// A via ldmatrix.x4, W streams from global blob with one-chunk register prefetch.
__device__ __forceinline__ void mma_layer(uint32_t sXa, const __half* __restrict__ gW,
                                          int nchunks, float acc[2][8][4]) {
    int lane = threadIdx.x & 31, warp = threadIdx.x >> 5;
    int rb = (warp & 3) * 32, h = warp >> 2;
    int rowA = rb + ((lane >> 3) & 1) * 8 + (lane & 7);
    int kofs = (lane >> 4) * 8;
    uint32_t aBase = sXa + (uint32_t)(rowA * PXH + kofs) * 2;
    const float4* wp = (const float4*)(gW + ((h * 32 + lane) * 32));
    float4 cur[4];
#pragma unroll
    for (int q = 0; q < 4; ++q) cur[q] = __ldg(wp + q);
    for (int kc = 0; kc < nchunks; ++kc) {
        int kn = (kc + 1 < nchunks) ? kc + 1 : kc;
        const float4* wn = (const float4*)((const __half*)wp + (size_t)kn * CHUNKH);
        float4 nxt[4];
#pragma unroll
        for (int q = 0; q < 4; ++q) nxt[q] = __ldg(wn + q);
        uint32_t A[2][4];
#pragma unroll
        for (int mt = 0; mt < 2; ++mt) {
            uint32_t a = aBase + (uint32_t)(mt * 16 * PXH * 2 + kc * 32);
            asm volatile("ldmatrix.sync.aligned.m8n8.x4.shared.b16 {%0,%1,%2,%3}, [%4];"
                         : "=r"(A[mt][0]), "=r"(A[mt][1]), "=r"(A[mt][2]), "=r"(A[mt][3])
                         : "r"(a));
        }
#pragma unroll
        for (int j = 0; j < 8; ++j) {
            uint32_t b0 = f4word(cur[j >> 1], (j & 1) * 2);
            uint32_t b1 = f4word(cur[j >> 1], (j & 1) * 2 + 1);
#pragma unroll
            for (int mt = 0; mt < 2; ++mt)
                mma_f16(acc[mt][j], A[mt][0], A[mt][1], A[mt][2], A[mt][3], b0, b1);
        }
#pragma unroll
        for (int q = 0; q < 4; ++q) cur[q] = nxt[q];
    }
}
__device__ __forceinline__ void acc_zero(float acc[2][8][4]) {
#pragma unroll
    for (int mt = 0; mt < 2; ++mt)
#pragma unroll
        for (int j = 0; j < 8; ++j)
#pragma unroll
            for (int q = 0; q < 4; ++q) acc[mt][j][q] = 0.0f;
}
// (+bias) + relu -> fp16 X in place via stmatrix.x4
template <bool BIAS>
__device__ __forceinline__ void epi_x(uint32_t sXa, float acc[2][8][4],
                                      const float* __restrict__ bias) {
    int lane = threadIdx.x & 31, warp = threadIdx.x >> 5;
    int rb = (warp & 3) * 32, h = warp >> 2;
    int tig = lane & 3;
    int rowS = rb + (lane >> 3) * 8 + (lane & 7);
    uint32_t sBase = sXa + (uint32_t)(rowS * PXH + h * 64) * 2;
#pragma unroll
    for (int j = 0; j < 8; ++j) {
        float bx = 0.f, by = 0.f;
        if (BIAS) {
            int c = h * 64 + j * 8 + tig * 2;
            bx = __ldg(bias + c); by = __ldg(bias + c + 1);
        }
        uint32_t w0 = packh2(fmaxf(acc[0][j][0] + bx, 0.f), fmaxf(acc[0][j][1] + by, 0.f));
        uint32_t w1 = packh2(fmaxf(acc[0][j][2] + bx, 0.f), fmaxf(acc[0][j][3] + by, 0.f));
        uint32_t w2 = packh2(fmaxf(acc[1][j][0] + bx, 0.f), fmaxf(acc[1][j][1] + by, 0.f));
        uint32_t w3 = packh2(fmaxf(acc[1][j][2] + bx, 0.f), fmaxf(acc[1][j][3] + by, 0.f));
        asm volatile("stmatrix.sync.aligned.m8n8.x4.shared.b16 [%0], {%1,%2,%3,%4};"
                     :: "r"(sBase + (uint32_t)(j * 16)), "r"(w0), "r"(w1), "r"(w2), "r"(w3)
                     : "memory");
    }
}
// acc + bias -> COALESCED f32 fragment-blob store (thread-owned float4 runs)
__device__ __forceinline__ void store_blob(float* __restrict__ gB, float acc[2][8][4],
                                           const float* __restrict__ bias) {
    int lane = threadIdx.x & 31, warp = threadIdx.x >> 5;
    int h = warp >> 2, tig = lane & 3;
    float* base = gB + warp * 2048 + lane * 4;
#pragma unroll
    for (int j = 0; j < 8; ++j) {
        int c = h * 64 + j * 8 + tig * 2;
        float bx = __ldg(bias + c), by = __ldg(bias + c + 1);
#pragma unroll
        for (int mt = 0; mt < 2; ++mt) {
            *(float4*)(base + (j * 2 + mt) * 128) =
                make_float4(acc[mt][j][0] + bx, acc[mt][j][1] + by,
                            acc[mt][j][2] + bx, acc[mt][j][3] + by);
        }
    }
}
// init acc from coalesced f32 fragment blob
__device__ __forceinline__ void load_blob(const float* __restrict__ gB, float acc[2][8][4]) {
    int lane = threadIdx.x & 31, warp = threadIdx.x >> 5;
    const float* base = gB + warp * 2048 + lane * 4;
#pragma unroll
    for (int j = 0; j < 8; ++j)
#pragma unroll
        for (int mt = 0; mt < 2; ++mt) {
            float4 v = __ldg((const float4*)(base + (j * 2 + mt) * 128));
            acc[mt][j][0] = v.x; acc[mt][j][1] = v.y;
            acc[mt][j][2] = v.z; acc[mt][j][3] = v.w;
        }
}
// relu -> vectorized f32 atomic scatter into g_agg[recv] (no bias; already in acc)
__device__ __forceinline__ void epi_scatter_nb(const int* __restrict__ recv, int e0,
                                               float acc[2][8][4]) {
    int lane = threadIdx.x & 31, warp = threadIdx.x >> 5;
    int rb = (warp & 3) * 32, h = warp >> 2;
    int g = lane >> 2, tig = lane & 3;
#pragma unroll
    for (int mt = 0; mt < 2; ++mt) {
        int ra = rb + mt * 16 + g;
        int va = __ldg(recv + e0 + ra), vb = __ldg(recv + e0 + ra + 8);
        float* pa = g_agg + (size_t)va * 128;
        float* pb = g_agg + (size_t)vb * 128;
#pragma unroll
        for (int j = 0; j < 8; ++j) {
            int c = h * 64 + j * 8 + tig * 2;
            red2(pa + c, fmaxf(acc[mt][j][0], 0.f), fmaxf(acc[mt][j][1], 0.f));
            red2(pb + c, fmaxf(acc[mt][j][2], 0.f), fmaxf(acc[mt][j][3], 0.f));
        }
    }
}
// staging copies (256 threads)
__device__ __forceinline__ void copy_out(__half* __restrict__ g, const __half* sX) {
    for (int i = threadIdx.x; i < 2048; i += 256) {
        int r = i >> 4, q = i & 15;
        ((float4*)g)[i] = ((const float4*)sX)[r * 17 + q];
    }
}
__device__ __forceinline__ void s_copy(__half* sX, const __half* __restrict__ g) {
    for (int i = threadIdx.x; i < 2048; i += 256) {
        int r = i >> 4, q = i & 15;
        ((float4*)sX)[r * 17 + q] = ((const float4*)g)[i];
    }
}
// f32 agg -> fp16 smem X
__device__ __forceinline__ void s_copy_cvt(__half* sX, const float* __restrict__ g) {
    for (int i = threadIdx.x; i < 4096; i += 256) {
        int r = i >> 5, q = i & 31;
        float4 v = ((const float4*)g)[i];
        uint2 u;
        u.x = packh2(v.x, v.y); u.y = packh2(v.z, v.w);
        ((uint2*)sX)[r * 34 + q] = u;
    }
}
// gather 128 rows src[idx[e0+r]] (fp16 row-major [p][128]) -> X
__device__ __forceinline__ void s_gather(__half* sX, const __half* __restrict__ src,
                                         const int* __restrict__ idx, int e0) {
    int row = threadIdx.x & 127, kq = threadIdx.x >> 7;
    int p = __ldg(idx + e0 + row);
    const float4* s4 = (const float4*)(src + (size_t)p * 128) + kq * 8;
    float4* d4 = (float4*)(sX + row * PXH) + kq * 8;
#pragma unroll
    for (int q = 0; q < 8; ++q) d4[q] = s4[q];
}

// ---------------- setup: fp16 weight blobs in B-fragment order ----------------
__global__ void k_mkblob(const float* __restrict__ pe_w0, const float* __restrict__ pe_w1,
                         const float* __restrict__ re_w0, const float* __restrict__ re_w1,
                         const float* __restrict__ re_w2, const float* __restrict__ rp_w,
                         const float* __restrict__ pp_w, const float* __restrict__ fl_w0,
                         const float* __restrict__ fl_w1) {
    int b = blockIdx.x;
    const float* src; __half* blob;
    int Kval, base;
    if (b < 2)        { src = pe_w0; blob = g_bPe0; Kval = 15;  base = 0; }
    else if (b < 10)  { src = pe_w1; blob = g_bPe1; Kval = 128; base = 2; }
    else if (b < 12)  { src = re_w0; blob = g_bRe0; Kval = 31;  base = 10; }
    else if (b < 20)  { src = re_w1; blob = g_bRe1; Kval = 128; base = 12; }
    else if (b < 28)  { src = re_w2; blob = g_bRe2; Kval = 128; base = 20; }
    else if (b < 52)  { src = rp_w;  blob = g_bRp;  Kval = 384; base = 28; }
    else if (b < 68)  { src = pp_w;  blob = g_bPp;  Kval = 256; base = 52; }
    else if (b < 76)  { src = fl_w0; blob = g_bFl0; Kval = 128; base = 68; }
    else              { src = fl_w1; blob = g_bFl1; Kval = 128; base = 76; }
    int kc = b - base;
    for (int i = threadIdx.x; i < CHUNKH; i += 256) {
        int h = i >> 10, rr = i & 1023, lane = rr >> 5, q = rr & 31;
        int j = q >> 2, u = q & 3;
        int n = h * 64 + j * 8 + (lane >> 2);
        int k = kc * 16 + (lane & 3) * 2 + (u & 1) + ((u >> 1) << 3);
        float v = (k < Kval) ? src[n * Kval + k] : 0.0f;
        blob[kc * CHUNKH + i] = __float2half_rn(v);
    }
}

__global__ void k_centroid(const float* __restrict__ state) {
    __shared__ float red[256];
    float s[6] = {0, 0, 0, 0, 0, 0};
    for (int r = threadIdx.x; r < RIGN; r += 256)
#pragma unroll
        for (int c = 0; c < 6; ++c) s[c] += state[r * 6 + c];
#pragma unroll
    for (int c = 0; c < 6; ++c) {
        red[threadIdx.x] = s[c];
        __syncthreads();
        for (int off = 128; off > 0; off >>= 1) {
            if (threadIdx.x < off) red[threadIdx.x] += red[threadIdx.x + off];
            __syncthreads();
        }
        if (threadIdx.x == 0) g_cent[c] = red[0] * (1.0f / RIGN);
        __syncthreads();
    }
}

// ---------------- particle encoder (+fused pp chunk 0): 15 -> 128 -> 128 -> peP ----------------
__global__ void __launch_bounds__(256, 2) k_pe(const float* __restrict__ state,
                                               const float* __restrict__ attr,
                                               const float* __restrict__ b0,
                                               const float* __restrict__ b1,
                                               const float* __restrict__ pp_b) {
    extern __shared__ __half sm_[];
    __half* sX = sm_;
    uint32_t sXa = (uint32_t)__cvta_generic_to_shared(sX);
    int t = threadIdx.x;
    int p0 = blockIdx.x * 128;
    {
        int row = t & 127, grp = t >> 7;
        int p = p0 + row;
        __half* xr = sX + row * PXH;
        if (grp == 0) {
#pragma unroll
            for (int c = 0; c < 3; ++c) xr[c] = __float2half_rn(attr[p * 3 + c]);
#pragma unroll
            for (int c = 0; c < 6; ++c) xr[9 + c] = __float2half_rn(state[p * 6 + c]);
        } else {
#pragma unroll
            for (int c = 0; c < 6; ++c) {
                float s = state[p * 6 + c];
                xr[3 + c] = (p < RIGN) ? __float2half_rn(s - g_cent[c]) : __half(0.0f);
            }
            for (int c = 15; c < 32; ++c) xr[c] = __half(0.0f);
        }
    }
    __syncthreads();
    float acc[2][8][4];
    acc_zero(acc);
    mma_layer(sXa, g_bPe0, 2, acc);
    __syncthreads();
    epi_x<true>(sXa, acc, b0);
    __syncthreads();
    acc_zero(acc);
    mma_layer(sXa, g_bPe1, 8, acc);
    __syncthreads();
    epi_x<true>(sXa, acc, b1);
    __syncthreads();
    // fused: peP = pp_w0 * particle_encode + pp_b   (blob layout, coalesced)
    acc_zero(acc);
    mma_layer(sXa, g_bPp, 8, acc);
    store_blob(g_peP + (size_t)blockIdx.x * 16384, acc, pp_b);
}

// ---------------- relation encoder (+fused rp chunk 0): 31 -> 128^3 -> relP ----------------
__global__ void __launch_bounds__(256, 2) k_rel(const float* __restrict__ state,
                                                const float* __restrict__ attr,
                                                const float* __restrict__ Ra,
                                                const int* __restrict__ recv,
                                                const int* __restrict__ send,
                                                const float* __restrict__ b0,
                                                const float* __restrict__ b1,
                                                const float* __restrict__ b2,
                                                const float* __restrict__ rp_b) {
    extern __shared__ __half sm_[];
    __half* sX = sm_;
    uint32_t sXa = (uint32_t)__cvta_generic_to_shared(sX);
    int t = threadIdx.x;
    int e0 = blockIdx.x * 128;
    {
        int row = t & 127, grp = t >> 7;
        int e = e0 + row;
        __half* xr = sX + row * PXH;
        if (grp == 0) {
            int rv = __ldg(recv + e);
#pragma unroll
            for (int c = 0; c < 3; ++c) xr[c] = __float2half_rn(attr[rv * 3 + c]);
#pragma unroll
            for (int c = 0; c < 6; ++c) {
                float s = state[rv * 6 + c];
                xr[3 + c] = (rv < RIGN) ? __float2half_rn(s - g_cent[c]) : __half(0.0f);
                xr[18 + c] = __float2half_rn(s);
            }
        } else {
            int sd = __ldg(send + e);
#pragma unroll
            for (int c = 0; c < 3; ++c) xr[9 + c] = __float2half_rn(attr[sd * 3 + c]);
#pragma unroll
            for (int c = 0; c < 6; ++c) {
                float s = state[sd * 6 + c];
                xr[12 + c] = (sd < RIGN) ? __float2half_rn(s - g_cent[c]) : __half(0.0f);
                xr[24 + c] = __float2half_rn(s);
            }
            xr[30] = __float2half_rn(Ra[e]);
            xr[31] = __half(0.0f);
        }
    }
    __syncthreads();
    float acc[2][8][4];
    acc_zero(acc);
    mma_layer(sXa, g_bRe0, 2, acc);
    __syncthreads();
    epi_x<true>(sXa, acc, b0);
    __syncthreads();
    acc_zero(acc);
    mma_layer(sXa, g_bRe1, 8, acc);
    __syncthreads();
    epi_x<true>(sXa, acc, b1);
    __syncthreads();
    acc_zero(acc);
    mma_layer(sXa, g_bRe2, 8, acc);
    __syncthreads();
    epi_x<true>(sXa, acc, b2);
    __syncthreads();
    // fused: relP = rp_w0 * relation_encode + rp_b  (blob layout, coalesced)
    acc_zero(acc);
    mma_layer(sXa, g_bRp, 8, acc);
    store_blob(g_relP + (size_t)blockIdx.x * 16384, acc, rp_b);
}

// ---------------- propagation step 1: relu(relP) scatter (blob walk, producer mapping) ----------------
__global__ void __launch_bounds__(256) k_scat1(const int* __restrict__ recv) {
    int lane = threadIdx.x & 31, warp = threadIdx.x >> 5;
    int rb = (warp & 3) * 32, h = warp >> 2;
    int g = lane >> 2, tig = lane & 3;
    int e0 = blockIdx.x * 128;
    const float* base = g_relP + (size_t)blockIdx.x * 16384 + warp * 2048 + lane * 4;
    int v0 = __ldg(recv + e0 + rb + g);        // rows for mt=0: r, r+8
    int v1 = __ldg(recv + e0 + rb + g + 8);
    int v2 = __ldg(recv + e0 + rb + 16 + g);   // rows for mt=1
    int v3 = __ldg(recv + e0 + rb + 24 + g);
    float* p0 = g_agg + (size_t)v0 * 128;
    float* p1 = g_agg + (size_t)v1 * 128;
    float* p2 = g_agg + (size_t)v2 * 128;
    float* p3 = g_agg + (size_t)v3 * 128;
#pragma unroll
    for (int j = 0; j < 8; ++j) {
        int c = h * 64 + j * 8 + tig * 2;
        float4 a = __ldg((const float4*)(base + (j * 2 + 0) * 128));
        float4 b = __ldg((const float4*)(base + (j * 2 + 1) * 128));
        red2(p0 + c, fmaxf(a.x, 0.f), fmaxf(a.y, 0.f));
        red2(p1 + c, fmaxf(a.z, 0.f), fmaxf(a.w, 0.f));
        red2(p2 + c, fmaxf(b.x, 0.f), fmaxf(b.y, 0.f));
        red2(p3 + c, fmaxf(b.z, 0.f), fmaxf(b.w, 0.f));
    }
}

// ---------------- propagation step 2 edge pass: relP + rp_w1*eff_r + rp_w2*eff_s ----------------
__global__ void __launch_bounds__(256, 2) k_prop(const int* __restrict__ recv,
                                                 const int* __restrict__ send,
                                                 const __half* __restrict__ eff) {
    extern __shared__ __half sm_[];
    __half* sX = sm_;
    uint32_t sXa = (uint32_t)__cvta_generic_to_shared(sX);
    int e0 = blockIdx.x * 128;
    s_gather(sX, eff, recv, e0);
    float acc[2][8][4];
    load_blob(g_relP + (size_t)blockIdx.x * 16384, acc);
    __syncthreads();
    mma_layer(sXa, g_bRp + 8 * CHUNKH, 8, acc);
    __syncthreads();
    s_gather(sX, eff, send, e0);
    __syncthreads();
    mma_layer(sXa, g_bRp + 16 * CHUNKH, 8, acc);
    epi_scatter_nb(recv, e0, acc);
}

// ---------------- particle update: peP + pp_w1*agg -> relu -> eff ----------------
__global__ void __launch_bounds__(256, 2) k_pupdate(__half* __restrict__ effOut) {
    extern __shared__ __half sm_[];
    __half* sX = sm_;
    uint32_t sXa = (uint32_t)__cvta_generic_to_shared(sX);
    int p0 = blockIdx.x * 128;
    s_copy_cvt(sX, g_agg + (size_t)p0 * 128);
    float acc[2][8][4];
    load_blob(g_peP + (size_t)blockIdx.x * 16384, acc);
    __syncthreads();
    mma_layer(sXa, g_bPp + 8 * CHUNKH, 8, acc);
    __syncthreads();
    epi_x<false>(sXa, acc, nullptr);
    __syncthreads();
    copy_out(effOut + (size_t)p0 * 128, sX);
}

// ---------------- rigid pooling + small MLP + rigid output ----------------
__global__ void k_pool(const __half* __restrict__ eff) {
    int f = threadIdx.x;  // 128
    int r0 = blockIdx.x * 128;
    float s = 0.0f;
    for (int r = 0; r < 128; ++r) s += __half2float(eff[(size_t)(r0 + r) * 128 + f]);
    atomicAdd(&g_pooled[f], s);
}

__global__ void k_rigid_mlp(const float* __restrict__ w0, const float* __restrict__ b0,
                            const float* __restrict__ w1, const float* __restrict__ b1,
                            const float* __restrict__ w2, const float* __restrict__ b2) {
    __shared__ float pin[128], h0[128], h1[128], tt[7];
    int t = threadIdx.x;  // 128
    pin[t] = g_pooled[t] * (1.0f / RIGN);
    __syncthreads();
    float s = b0[t];
    for (int k = 0; k < 128; ++k) s = fmaf(w0[t * 128 + k], pin[k], s);
    h0[t] = fmaxf(s, 0.0f);
    __syncthreads();
    s = b1[t];
    for (int k = 0; k < 128; ++k) s = fmaf(w1[t * 128 + k], h0[k], s);
    h1[t] = fmaxf(s, 0.0f);
    __syncthreads();
    if (t < 7) {
        s = b2[t];
        for (int k = 0; k < 128; ++k) s = fmaf(w2[t * 128 + k], h1[k], s);
        tt[t] = s;
    }
    __syncthreads();
    if (t == 0) {
        float qw = tt[0], qx = tt[1], qy = tt[2], qz = tt[3];
        float inv = rsqrtf(qw * qw + qx * qx + qy * qy + qz * qz);
        qw *= inv; qx *= inv; qy *= inv; qz *= inv;
        g_Rmat[0] = 1.0f - 2.0f * (qy * qy + qz * qz);
        g_Rmat[1] = 2.0f * (qx * qy + qz * qw);
        g_Rmat[2] = 2.0f * (qx * qz - qy * qw);
        g_Rmat[3] = 2.0f * (qx * qy - qz * qw);
        g_Rmat[4] = 1.0f - 2.0f * (qx * qx + qz * qz);
        g_Rmat[5] = 2.0f * (qy * qz + qx * qw);
        g_Rmat[6] = 2.0f * (qx * qz + qy * qw);
        g_Rmat[7] = 2.0f * (qy * qz - qx * qw);
        g_Rmat[8] = 1.0f - 2.0f * (qx * qx + qy * qy);
        g_tb[0] = tt[4]; g_tb[1] = tt[5]; g_tb[2] = tt[6];
    }
}

__global__ void k_rigid_out(const float* __restrict__ state, float* __restrict__ out) {
    int i = blockIdx.x * 256 + threadIdx.x;
    if (i >= RIGN) return;
    float c0 = g_cent[0], c1 = g_cent[1], c2 = g_cent[2];
    float p0x = state[i * 6], p0y = state[i * 6 + 1], p0z = state[i * 6 + 2];
    float dx = p0x - c0, dy = p0y - c1, dz = p0z - c2;
    float p1x = dx * g_Rmat[0] + dy * g_Rmat[3] + dz * g_Rmat[6] + g_tb[0] + c0;
    float p1y = dx * g_Rmat[1] + dy * g_Rmat[4] + dz * g_Rmat[7] + g_tb[1] + c1;
    float p1z = dx * g_Rmat[2] + dy * g_Rmat[5] + dz * g_Rmat[8] + g_tb[2] + c2;
    out[i * 3] = (p1x - p0x) * DT_INV;
    out[i * 3 + 1] = (p1y - p0y) * DT_INV;
    out[i * 3 + 2] = (p1z - p0z) * DT_INV;
}

// ---------------- fluid predictor: 128 -> 128 -> 128 -> 3 ----------------
__global__ void __launch_bounds__(256, 2) k_fluid(const __half* __restrict__ eff,
                                                  const float* __restrict__ fb0,
                                                  const float* __restrict__ fb1,
                                                  const float* __restrict__ fw2,
                                                  const float* __restrict__ fb2,
                                                  float* __restrict__ out) {
    extern __shared__ __half sm_[];
    __half* sX = sm_;
    uint32_t sXa = (uint32_t)__cvta_generic_to_shared(sX);
    int t = threadIdx.x;
    s_copy(sX, eff + (size_t)(32 + blockIdx.x) * 16384);
    __syncthreads();
    float acc[2][8][4];
    acc_zero(acc);
    mma_layer(sXa, g_bFl0, 8, acc);
    __syncthreads();
    epi_x<true>(sXa, acc, fb0);
    __syncthreads();
    acc_zero(acc);
    mma_layer(sXa, g_bFl1, 8, acc);
    __syncthreads();
    epi_x<true>(sXa, acc, fb1);
    __syncthreads();
    {
        int row = t & 127, grp = t >> 7;
        int p = RIGN + blockIdx.x * 128 + row;
        const __half* xr = sX + row * PXH;
        for (int ch = grp; ch < 3; ch += 2) {
            float o = __ldg(fb2 + ch);
            const float* wr = fw2 + ch * 128;
            for (int k = 0; k < 128; ++k) o = fmaf(__ldg(wr + k), __half2float(xr[k]), o);
            out[(size_t)p * 3 + ch] = o;
        }
    }
}

// ---------------- launch ----------------
extern "C" void kernel_launch(void* const* d_in, const int* in_sizes, int n_in,
                              void* d_out, int out_size) {
    const float* state = (const float*)d_in[0];
    const float* attr = (const float*)d_in[1];
    const float* Ra = (const float*)d_in[2];
    const int* recv = (const int*)d_in[3];
    const int* send = (const int*)d_in[4];
    const float* pe_w0 = (const float*)d_in[5];
    const float* pe_b0 = (const float*)d_in[6];
    const float* pe_w1 = (const float*)d_in[7];
    const float* pe_b1 = (const float*)d_in[8];
    const float* re_w0 = (const float*)d_in[9];
    const float* re_b0 = (const float*)d_in[10];
    const float* re_w1 = (const float*)d_in[11];
    const float* re_b1 = (const float*)d_in[12];
    const float* re_w2 = (const float*)d_in[13];
    const float* re_b2 = (const float*)d_in[14];
    const float* rp_w = (const float*)d_in[15];
    const float* rp_b = (const float*)d_in[16];
    const float* pp_w = (const float*)d_in[17];
    const float* pp_b = (const float*)d_in[18];
    const float* rg_w0 = (const float*)d_in[19];
    const float* rg_b0 = (const float*)d_in[20];
    const float* rg_w1 = (const float*)d_in[21];
    const float* rg_b1 = (const float*)d_in[22];
    const float* rg_w2 = (const float*)d_in[23];
    const float* rg_b2 = (const float*)d_in[24];
    const float* fl_w0 = (const float*)d_in[25];
    const float* fl_b0 = (const float*)d_in[26];
    const float* fl_w1 = (const float*)d_in[27];
    const float* fl_b1 = (const float*)d_in[28];
    const float* fl_w2 = (const float*)d_in[29];
    const float* fl_b2 = (const float*)d_in[30];
    float* out = (float*)d_out;

    cudaFuncSetAttribute(k_pe, cudaFuncAttributeMaxDynamicSharedMemorySize, SMEMSZ);
    cudaFuncSetAttribute(k_rel, cudaFuncAttributeMaxDynamicSharedMemorySize, SMEMSZ);
    cudaFuncSetAttribute(k_prop, cudaFuncAttributeMaxDynamicSharedMemorySize, SMEMSZ);
    cudaFuncSetAttribute(k_pupdate, cudaFuncAttributeMaxDynamicSharedMemorySize, SMEMSZ);
    cudaFuncSetAttribute(k_fluid, cudaFuncAttributeMaxDynamicSharedMemorySize, SMEMSZ);

    float* aggp; float* pooledp; __half* eff1p; __half* eff2p;
    cudaGetSymbolAddress((void**)&aggp, g_agg);
    cudaGetSymbolAddress((void**)&pooledp, g_pooled);
    cudaGetSymbolAddress((void**)&eff1p, g_eff1);
    cudaGetSymbolAddress((void**)&eff2p, g_eff2);

    k_mkblob<<<84, 256>>>(pe_w0, pe_w1, re_w0, re_w1, re_w2, rp_w, pp_w, fl_w0, fl_w1);
    k_centroid<<<1, 256>>>(state);
    k_pe<<<NP / 128, 256, SMEMSZ>>>(state, attr, pe_b0, pe_b1, pp_b);
    k_rel<<<NE / 128, 256, SMEMSZ>>>(state, attr, Ra, recv, send, re_b0, re_b1, re_b2, rp_b);

    // propagation step 1: effect==0 -> scatter relu(relP) only
    cudaMemsetAsync(aggp, 0, (size_t)NP * 128 * sizeof(float));
    k_scat1<<<NE / 128, 256>>>(recv);
    k_pupdate<<<NP / 128, 256, SMEMSZ>>>(eff1p);

    // propagation step 2
    cudaMemsetAsync(aggp, 0, (size_t)NP * 128 * sizeof(float));
    k_prop<<<NE / 128, 256, SMEMSZ>>>(recv, send, eff1p);
    k_pupdate<<<NP / 128, 256, SMEMSZ>>>(eff2p);

    // rigid branch
    cudaMemsetAsync(pooledp, 0, 128 * sizeof(float));
    k_pool<<<RIGN / 128, 128>>>(eff2p);
    k_rigid_mlp<<<1, 128>>>(rg_w0, rg_b0, rg_w1, rg_b1, rg_w2, rg_b2);
    k_rigid_out<<<RIGN / 256, 256>>>(state, out);

    // fluid branch
    k_fluid<<<(NP - RIGN) / 128, 256, SMEMSZ>>>(eff2p, fl_b0, fl_b1, fl_w2, fl_b2, out);
}